// round 1
// baseline (speedup 1.0000x reference)
#include <cuda_runtime.h>
#include <cuda_bf16.h>

// ---------------------------------------------------------------------------
// SNN: out[t,b,o] = mem2 trajectory of
//   cur1 = x_t @ W1^T                          (big GEMM, time-parallel)
//   reset = (mem1_prev > 1); mem1 = 0.95*mem1 + cur1 - reset
//   spk   = (mem1 > 1);      mem2 = 0.95*mem2 + spk @ W2^T
//
// Kernel 1: dense fp32 GEMM  cur[m,h] = sum_k x[m,k]*W1[h,k], m = b*T + t
// Kernel 2: one CTA per batch element runs the 128-step scan entirely on-chip
// ---------------------------------------------------------------------------

#define BATCH   256
#define T_STEPS 128
#define K_IN    1156
#define N_HID   1024
#define N_OUT   10
#define M_TOTAL (BATCH * T_STEPS)   // 32768

// Scratch: cur[m][h], 32768 x 1024 fp32 = 134 MB (static device array: allowed)
__device__ float g_cur[(size_t)M_TOTAL * N_HID];

// ---------------------------- GEMM ----------------------------------------
#define BM 128
#define BN 128
#define BK 8
#define SMS 132   // padded stride (132*4B = 528B, 16B-aligned, kills bank conflicts)

__global__ __launch_bounds__(256, 2)
void snn_gemm_kernel(const float* __restrict__ A,   // x  [M_TOTAL, K_IN]
                     const float* __restrict__ B)   // W1 [N_HID,  K_IN]
{
    __shared__ float As[BK][SMS];
    __shared__ float Bs[BK][SMS];

    const int tid  = threadIdx.x;          // 256 threads
    const int tx   = tid & 15;             // 16 x 16 thread grid
    const int ty   = tid >> 4;
    const int m0   = blockIdx.y * BM;
    const int n0   = blockIdx.x * BN;

    // loading map: thread -> (row, 4 consecutive k)
    const int lrow = tid >> 1;             // 0..127
    const int lk   = (tid & 1) * 4;        // 0 or 4

    const float* Arow = A + (size_t)(m0 + lrow) * K_IN;
    const float* Brow = B + (size_t)(n0 + lrow) * K_IN;

    float acc[8][8];
#pragma unroll
    for (int i = 0; i < 8; i++)
#pragma unroll
        for (int j = 0; j < 8; j++) acc[i][j] = 0.f;

    for (int kb = 0; kb < K_IN; kb += BK) {
#pragma unroll
        for (int i = 0; i < 4; i++) {
            int k = kb + lk + i;
            As[lk + i][lrow] = (k < K_IN) ? Arow[k] : 0.f;
            Bs[lk + i][lrow] = (k < K_IN) ? Brow[k] : 0.f;
        }
        __syncthreads();

#pragma unroll
        for (int kk = 0; kk < BK; kk++) {
            float4 a0 = *(const float4*)&As[kk][ty * 8];
            float4 a1 = *(const float4*)&As[kk][ty * 8 + 4];
            float4 b0 = *(const float4*)&Bs[kk][tx * 8];
            float4 b1 = *(const float4*)&Bs[kk][tx * 8 + 4];
            float a[8] = {a0.x, a0.y, a0.z, a0.w, a1.x, a1.y, a1.z, a1.w};
            float b[8] = {b0.x, b0.y, b0.z, b0.w, b1.x, b1.y, b1.z, b1.w};
#pragma unroll
            for (int i = 0; i < 8; i++)
#pragma unroll
                for (int j = 0; j < 8; j++)
                    acc[i][j] += a[i] * b[j];
        }
        __syncthreads();
    }

    // store C tile to g_cur
#pragma unroll
    for (int i = 0; i < 8; i++) {
        size_t row = (size_t)(m0 + ty * 8 + i);
        float* dst = g_cur + row * N_HID + n0 + tx * 8;
        *(float4*)dst       = make_float4(acc[i][0], acc[i][1], acc[i][2], acc[i][3]);
        *(float4*)(dst + 4) = make_float4(acc[i][4], acc[i][5], acc[i][6], acc[i][7]);
    }
}

// ---------------------------- Scan ----------------------------------------
// One CTA per batch element b. 1024 threads; thread h owns mem1[b,h] in a
// register. Per step: elementwise LIF update, spike, then a 1024 -> 10
// weighted reduction (warp shuffles + 32x10 shared tree) for mem2.
__global__ __launch_bounds__(1024)
void snn_scan_kernel(const float* __restrict__ W2,   // [N_OUT, N_HID]
                     float* __restrict__ out)        // [T, B, N_OUT]
{
    const int b    = blockIdx.x;
    const int h    = threadIdx.x;
    const int lane = h & 31;
    const int warp = h >> 5;

    float w2[N_OUT];
#pragma unroll
    for (int o = 0; o < N_OUT; o++) w2[o] = W2[o * N_HID + h];

    __shared__ float red[32][N_OUT];
    __shared__ float mem2[N_OUT];
    if (h < N_OUT) mem2[h] = 0.f;

    float mem1 = 0.f;
    const float* curb = g_cur + (size_t)b * T_STEPS * N_HID;

    for (int t = 0; t < T_STEPS; t++) {
        float c = curb[t * N_HID + h];

        // reset from PREVIOUS mem1, then leak+input, then spike on NEW mem1
        float reset = (mem1 > 1.0f) ? 1.0f : 0.0f;
        mem1 = 0.95f * mem1 + c - reset;
        bool spk = (mem1 > 1.0f);

        float p[N_OUT];
#pragma unroll
        for (int o = 0; o < N_OUT; o++) p[o] = spk ? w2[o] : 0.f;

#pragma unroll
        for (int o = 0; o < N_OUT; o++) {
            p[o] += __shfl_down_sync(0xffffffffu, p[o], 16);
            p[o] += __shfl_down_sync(0xffffffffu, p[o], 8);
            p[o] += __shfl_down_sync(0xffffffffu, p[o], 4);
            p[o] += __shfl_down_sync(0xffffffffu, p[o], 2);
            p[o] += __shfl_down_sync(0xffffffffu, p[o], 1);
        }
        if (lane == 0) {
#pragma unroll
            for (int o = 0; o < N_OUT; o++) red[warp][o] = p[o];
        }
        __syncthreads();

        if (h < N_OUT) {
            float s = 0.f;
#pragma unroll
            for (int w = 0; w < 32; w++) s += red[w][h];
            float m2 = 0.95f * mem2[h] + s;
            mem2[h] = m2;
            out[((size_t)t * BATCH + b) * N_OUT + h] = m2;
        }
        __syncthreads();
    }
}

// ---------------------------- Launch ---------------------------------------
extern "C" void kernel_launch(void* const* d_in, const int* in_sizes, int n_in,
                              void* d_out, int out_size)
{
    const float* x  = (const float*)d_in[0];   // [B, T, K_IN]  (rows m = b*T+t)
    const float* W1 = (const float*)d_in[1];   // [N_HID, K_IN]
    const float* W2 = (const float*)d_in[2];   // [N_OUT, N_HID]
    float* out = (float*)d_out;                // [T, B, N_OUT]

    dim3 grid(N_HID / BN, M_TOTAL / BM);       // 8 x 256
    snn_gemm_kernel<<<grid, 256>>>(x, W1);
    snn_scan_kernel<<<BATCH, 1024>>>(W2, out);
}

// round 6
// speedup vs baseline: 1.3016x; 1.3016x over previous
#include <cuda_runtime.h>
#include <cuda_bf16.h>
#include <cstdint>

// ---------------------------------------------------------------------------
// SNN on B200 (compute_100 virtual => mma.sync tf32, 4-term split,
//              per-K-tile accumulator drain to fp32 registers)
//
//   K1: cur = x @ W1^T tile (128x128) via 4xTF32 split mma.sync.
//       TC accumulators are zeroed every K-tile and drained into plain fp32
//       register sums (kills the long biased TC add-chain), fused epilogue
//       runs the LIF mem1 recurrence and emits spikes (bf16) -> g_spk.
//   K2: cur2[m, o] = spk[m, :] @ W2[o, :]   (warp per row, exact products)
//   K3: mem2 leaky integration (2560 independent scans)
// ---------------------------------------------------------------------------

#define BATCH   256
#define T_STEPS 128
#define K_IN    1156
#define N_HID   1024
#define N_OUT   10
#define M_TOTAL (BATCH * T_STEPS)   // 32768
#define KTILES  37                  // ceil(1156/32)
#define SA      36                  // smem row stride (floats)

__device__ __nv_bfloat16 g_spk[(size_t)M_TOTAL * N_HID];   // 64 MB
__device__ float         g_cur2[(size_t)M_TOTAL * N_OUT];  // 1.3 MB

// ===================== helpers =============================================
__device__ __forceinline__ uint32_t smem_u32(const void* p) {
    uint32_t a;
    asm("{ .reg .u64 t; cvta.to.shared.u64 t, %1; cvt.u32.u64 %0, t; }"
        : "=r"(a) : "l"(p));
    return a;
}

__device__ __forceinline__ void cp_async16(uint32_t dst, const void* src, int bytes) {
    asm volatile("cp.async.cg.shared.global [%0], [%1], 16, %2;"
                 :: "r"(dst), "l"(src), "r"(bytes));
}
#define CP_COMMIT() asm volatile("cp.async.commit_group;" ::: "memory")
#define CP_WAIT1()  asm volatile("cp.async.wait_group 1;" ::: "memory")

// split fp32 into tf32 hi + tf32 lo (rna)
__device__ __forceinline__ void split1(float v, uint32_t& hi, uint32_t& lo) {
    asm("cvt.rna.tf32.f32 %0, %1;" : "=r"(hi) : "f"(v));
    float l = v - __uint_as_float(hi);
    asm("cvt.rna.tf32.f32 %0, %1;" : "=r"(lo) : "f"(l));
}

__device__ __forceinline__ void mma8(float* c, const uint32_t* a, const uint32_t* b) {
    asm volatile(
        "mma.sync.aligned.m16n8k8.row.col.f32.tf32.tf32.f32 "
        "{%0,%1,%2,%3}, {%4,%5,%6,%7}, {%8,%9}, {%0,%1,%2,%3};"
        : "+f"(c[0]), "+f"(c[1]), "+f"(c[2]), "+f"(c[3])
        : "r"(a[0]), "r"(a[1]), "r"(a[2]), "r"(a[3]), "r"(b[0]), "r"(b[1]));
}

// ===================== K1: GEMM + fused spike scan =========================
#define STAGE_FLOATS (2 * 128 * SA)          // 9216
#define GEMM_SMEM    (2 * STAGE_FLOATS * 4)  // 73728 B (covers 128x132 cur tile)

__global__ __launch_bounds__(256, 1)
void snn_gemm_spike(const float* __restrict__ A,   // x  [M_TOTAL, K_IN]
                    const float* __restrict__ B)   // W1 [N_HID,  K_IN]
{
    extern __shared__ float sm[];
    const uint32_t sbase = smem_u32(sm);
    const int tid  = threadIdx.x;
    const int wid  = tid >> 5;
    const int lane = tid & 31;
    const int wm   = wid >> 2;      // 0..1 -> 64 rows each
    const int wn   = wid & 3;       // 0..3 -> 32 cols each
    const int b    = blockIdx.y;    // one batch element = 128 rows (all T)
    const int n0   = blockIdx.x * 128;

    const float* Abase = A + (size_t)b * 128 * K_IN;
    const float* Bbase = B + (size_t)n0 * K_IN;

    float sum[4][4][4];    // running fp32 sums (drained per K-tile)
#pragma unroll
    for (int i = 0; i < 4; i++)
#pragma unroll
        for (int j = 0; j < 4; j++)
#pragma unroll
            for (int q = 0; q < 4; q++) sum[i][j][q] = 0.f;

    auto prefetch = [&](int it) {
        const int s  = it & 1;
        const int kb = it * 32;
        const uint32_t sA = sbase + (uint32_t)s * STAGE_FLOATS * 4;
        const uint32_t sB = sA + 128 * SA * 4;
#pragma unroll
        for (int i = 0; i < 4; ++i) {
            const int f   = tid + i * 256;   // 0..1023
            const int row = f >> 3;
            const int j   = f & 7;
            const int k0  = kb + j * 4;
            int rem = K_IN - k0;
            int bytes = rem <= 0 ? 0 : (rem >= 4 ? 16 : rem * 4);
            const int ksafe = (k0 < K_IN) ? k0 : 0;
            const uint32_t off = (uint32_t)(row * SA + j * 4) * 4;
            cp_async16(sA + off, Abase + (size_t)row * K_IN + ksafe, bytes);
            cp_async16(sB + off, Bbase + (size_t)row * K_IN + ksafe, bytes);
        }
    };

    prefetch(0);
    CP_COMMIT();

    const int g  = lane >> 2;   // 0..7
    const int tg = lane & 3;    // 0..3

    for (int it = 0; it < KTILES; ++it) {
        if (it + 1 < KTILES) prefetch(it + 1);
        CP_COMMIT();
        CP_WAIT1();
        __syncthreads();

        const int s = it & 1;
        const float* As = sm + s * STAGE_FLOATS;
        const float* Bs = As + 128 * SA;

        // per-tile TC accumulators (zeroed each tile: short biased add chains)
        float accM[4][4][4];
        float accC[4][4][4];
#pragma unroll
        for (int i = 0; i < 4; i++)
#pragma unroll
            for (int j = 0; j < 4; j++)
#pragma unroll
                for (int q = 0; q < 4; q++) { accM[i][j][q] = 0.f; accC[i][j][q] = 0.f; }

#pragma unroll
        for (int ks = 0; ks < 4; ++ks) {
            uint32_t ahi[4][4], alo[4][4], bhi[4][2], blo[4][2];
#pragma unroll
            for (int mi = 0; mi < 4; ++mi) {
                const int r = wm * 64 + mi * 16 + g;
                const int c = ks * 8 + tg;
                split1(As[r * SA + c],           ahi[mi][0], alo[mi][0]);
                split1(As[(r + 8) * SA + c],     ahi[mi][1], alo[mi][1]);
                split1(As[r * SA + c + 4],       ahi[mi][2], alo[mi][2]);
                split1(As[(r + 8) * SA + c + 4], ahi[mi][3], alo[mi][3]);
            }
#pragma unroll
            for (int ni = 0; ni < 4; ++ni) {
                const int n = wn * 32 + ni * 8 + g;
                const int k = ks * 8 + tg;
                split1(Bs[n * SA + k],     bhi[ni][0], blo[ni][0]);
                split1(Bs[n * SA + k + 4], bhi[ni][1], blo[ni][1]);
            }
#pragma unroll
            for (int mi = 0; mi < 4; ++mi)
#pragma unroll
                for (int ni = 0; ni < 4; ++ni) {
                    mma8(accM[mi][ni], ahi[mi], bhi[ni]);
                    mma8(accC[mi][ni], ahi[mi], blo[ni]);
                    mma8(accC[mi][ni], alo[mi], bhi[ni]);
                    mma8(accC[mi][ni], alo[mi], blo[ni]);
                }
        }

        // drain tile partials into fp32 register sums
#pragma unroll
        for (int mi = 0; mi < 4; ++mi)
#pragma unroll
            for (int ni = 0; ni < 4; ++ni)
#pragma unroll
                for (int q = 0; q < 4; ++q)
                    sum[mi][ni][q] += (accM[mi][ni][q] + accC[mi][ni][q]);

        __syncthreads();
    }

    // ---- epilogue: sums -> SMEM cur tile [128 t][132], LIF scan ----
    float* cur = sm;   // 128*132*4 = 67584 <= 73728
#pragma unroll
    for (int mi = 0; mi < 4; ++mi)
#pragma unroll
        for (int ni = 0; ni < 4; ++ni) {
            const int r = wm * 64 + mi * 16 + g;
            const int c = wn * 32 + ni * 8 + tg * 2;
            cur[r * 132 + c]           = sum[mi][ni][0];
            cur[r * 132 + c + 1]       = sum[mi][ni][1];
            cur[(r + 8) * 132 + c]     = sum[mi][ni][2];
            cur[(r + 8) * 132 + c + 1] = sum[mi][ni][3];
        }
    __syncthreads();

    if (tid < 128) {
        float mem1 = 0.f;
        __nv_bfloat16* dst = g_spk + (size_t)b * 128 * N_HID + n0 + tid;
#pragma unroll 4
        for (int t = 0; t < T_STEPS; ++t) {
            const float cv = cur[t * 132 + tid];
            const float reset = (mem1 > 1.0f) ? 1.0f : 0.0f;
            mem1 = 0.95f * mem1 + cv - reset;
            dst[(size_t)t * N_HID] = __float2bfloat16((mem1 > 1.0f) ? 1.0f : 0.0f);
        }
    }
}

// ===================== K2: cur2 = spk @ W2^T ================================
__global__ __launch_bounds__(256)
void snn_gemm2(const float* __restrict__ W2)   // [N_OUT, N_HID]
{
    __shared__ float w2s[N_HID * 11];
    const int tid  = threadIdx.x;
    const int wid  = tid >> 5;
    const int lane = tid & 31;

    for (int i = tid; i < N_HID * N_OUT; i += 256) {
        const int h = i / N_OUT;
        const int o = i - h * N_OUT;
        w2s[h * 11 + o] = W2[o * N_HID + h];
    }
    __syncthreads();

    const size_t m = (size_t)blockIdx.x * 8 + wid;
    const __nv_bfloat16* srow = g_spk + m * N_HID;

    float acc[N_OUT];
#pragma unroll
    for (int o = 0; o < N_OUT; o++) acc[o] = 0.f;

#pragma unroll 4
    for (int j = 0; j < 32; ++j) {
        const int h = lane + j * 32;
        const float s = __bfloat162float(srow[h]);
        if (s != 0.f) {
#pragma unroll
            for (int o = 0; o < N_OUT; o++) acc[o] += w2s[h * 11 + o];
        }
    }

#pragma unroll
    for (int o = 0; o < N_OUT; o++) {
        acc[o] += __shfl_down_sync(0xffffffffu, acc[o], 16);
        acc[o] += __shfl_down_sync(0xffffffffu, acc[o], 8);
        acc[o] += __shfl_down_sync(0xffffffffu, acc[o], 4);
        acc[o] += __shfl_down_sync(0xffffffffu, acc[o], 2);
        acc[o] += __shfl_down_sync(0xffffffffu, acc[o], 1);
    }
    if (lane == 0) {
#pragma unroll
        for (int o = 0; o < N_OUT; o++) g_cur2[m * N_OUT + o] = acc[o];
    }
}

// ===================== K3: mem2 leaky integration ==========================
__global__ void snn_scan2(float* __restrict__ out)   // [T, B, N_OUT]
{
    const int id = blockIdx.x * 256 + threadIdx.x;
    if (id >= BATCH * N_OUT) return;
    const int bb = id / N_OUT;
    const int o  = id - bb * N_OUT;

    float m2 = 0.f;
    for (int t = 0; t < T_STEPS; ++t) {
        m2 = 0.95f * m2 + g_cur2[((size_t)bb * T_STEPS + t) * N_OUT + o];
        out[((size_t)t * BATCH + bb) * N_OUT + o] = m2;
    }
}

// ===================== launch ==============================================
extern "C" void kernel_launch(void* const* d_in, const int* in_sizes, int n_in,
                              void* d_out, int out_size)
{
    const float* x  = (const float*)d_in[0];   // [B, T, K_IN]
    const float* W1 = (const float*)d_in[1];   // [N_HID, K_IN]
    const float* W2 = (const float*)d_in[2];   // [N_OUT, N_HID]
    float* out = (float*)d_out;                // [T, B, N_OUT]

    cudaFuncSetAttribute(snn_gemm_spike,
                         cudaFuncAttributeMaxDynamicSharedMemorySize, GEMM_SMEM);

    dim3 grid1(N_HID / 128, M_TOTAL / 128);    // (8, 256)
    snn_gemm_spike<<<grid1, 256, GEMM_SMEM>>>(x, W1);
    snn_gemm2<<<M_TOTAL / 8, 256>>>(W2);
    snn_scan2<<<(BATCH * N_OUT + 255) / 256, 256>>>(out);
}

// round 7
// speedup vs baseline: 1.6719x; 1.2845x over previous
#include <cuda_runtime.h>
#include <cuda_bf16.h>
#include <cstdint>

// ---------------------------------------------------------------------------
// SNN on B200 (compute_100 virtual => mma.sync tf32, 3-term split,
//              single per-K-tile TC accumulator drained to fp32 registers)
//
//   K1: cur = x @ W1^T tile (128x128) via 3xTF32 split mma.sync
//       (hi*hi + hi*lo + lo*hi into ONE per-tile acc, drained per K-tile),
//       fused epilogue: LIF mem1 recurrence, spikes (bf16) -> g_spk.
//   K2: cur2[m, o] = spk[m, :] @ W2[o, :]   (warp per row, exact products)
//   K3: mem2 leaky integration (2560 independent scans)
// ---------------------------------------------------------------------------

#define BATCH   256
#define T_STEPS 128
#define K_IN    1156
#define N_HID   1024
#define N_OUT   10
#define M_TOTAL (BATCH * T_STEPS)   // 32768
#define KTILES  37                  // ceil(1156/32)
#define SA      36                  // smem row stride (floats)

__device__ __nv_bfloat16 g_spk[(size_t)M_TOTAL * N_HID];   // 64 MB
__device__ float         g_cur2[(size_t)M_TOTAL * N_OUT];  // 1.3 MB

// ===================== helpers =============================================
__device__ __forceinline__ uint32_t smem_u32(const void* p) {
    uint32_t a;
    asm("{ .reg .u64 t; cvta.to.shared.u64 t, %1; cvt.u32.u64 %0, t; }"
        : "=r"(a) : "l"(p));
    return a;
}

__device__ __forceinline__ void cp_async16(uint32_t dst, const void* src, int bytes) {
    asm volatile("cp.async.cg.shared.global [%0], [%1], 16, %2;"
                 :: "r"(dst), "l"(src), "r"(bytes));
}
#define CP_COMMIT() asm volatile("cp.async.commit_group;" ::: "memory")
#define CP_WAIT1()  asm volatile("cp.async.wait_group 1;" ::: "memory")

// split fp32 into tf32 hi + tf32 lo (rna)
__device__ __forceinline__ void split1(float v, uint32_t& hi, uint32_t& lo) {
    asm("cvt.rna.tf32.f32 %0, %1;" : "=r"(hi) : "f"(v));
    float l = v - __uint_as_float(hi);
    asm("cvt.rna.tf32.f32 %0, %1;" : "=r"(lo) : "f"(l));
}

__device__ __forceinline__ void mma8(float* c, const uint32_t* a, const uint32_t* b) {
    asm volatile(
        "mma.sync.aligned.m16n8k8.row.col.f32.tf32.tf32.f32 "
        "{%0,%1,%2,%3}, {%4,%5,%6,%7}, {%8,%9}, {%0,%1,%2,%3};"
        : "+f"(c[0]), "+f"(c[1]), "+f"(c[2]), "+f"(c[3])
        : "r"(a[0]), "r"(a[1]), "r"(a[2]), "r"(a[3]), "r"(b[0]), "r"(b[1]));
}

// ===================== K1: GEMM + fused spike scan =========================
#define STAGE_FLOATS (2 * 128 * SA)          // 9216
#define GEMM_SMEM    (2 * STAGE_FLOATS * 4)  // 73728 B (covers 128x132 cur tile)

__global__ __launch_bounds__(256, 1)
void snn_gemm_spike(const float* __restrict__ A,   // x  [M_TOTAL, K_IN]
                    const float* __restrict__ B)   // W1 [N_HID,  K_IN]
{
    extern __shared__ float sm[];
    const uint32_t sbase = smem_u32(sm);
    const int tid  = threadIdx.x;
    const int wid  = tid >> 5;
    const int lane = tid & 31;
    const int wm   = wid >> 2;      // 0..1 -> 64 rows each
    const int wn   = wid & 3;       // 0..3 -> 32 cols each
    const int b    = blockIdx.y;    // one batch element = 128 rows (all T)
    const int n0   = blockIdx.x * 128;

    const float* Abase = A + (size_t)b * 128 * K_IN;
    const float* Bbase = B + (size_t)n0 * K_IN;

    float sum[4][4][4];    // running fp32 sums (drained per K-tile)
#pragma unroll
    for (int i = 0; i < 4; i++)
#pragma unroll
        for (int j = 0; j < 4; j++)
#pragma unroll
            for (int q = 0; q < 4; q++) sum[i][j][q] = 0.f;

    auto prefetch = [&](int it) {
        const int s  = it & 1;
        const int kb = it * 32;
        const uint32_t sA = sbase + (uint32_t)s * STAGE_FLOATS * 4;
        const uint32_t sB = sA + 128 * SA * 4;
#pragma unroll
        for (int i = 0; i < 4; ++i) {
            const int f   = tid + i * 256;   // 0..1023
            const int row = f >> 3;
            const int j   = f & 7;
            const int k0  = kb + j * 4;
            int rem = K_IN - k0;
            int bytes = rem <= 0 ? 0 : (rem >= 4 ? 16 : rem * 4);
            const int ksafe = (k0 < K_IN) ? k0 : 0;
            const uint32_t off = (uint32_t)(row * SA + j * 4) * 4;
            cp_async16(sA + off, Abase + (size_t)row * K_IN + ksafe, bytes);
            cp_async16(sB + off, Bbase + (size_t)row * K_IN + ksafe, bytes);
        }
    };

    prefetch(0);
    CP_COMMIT();

    const int g  = lane >> 2;   // 0..7
    const int tg = lane & 3;    // 0..3

    for (int it = 0; it < KTILES; ++it) {
        if (it + 1 < KTILES) prefetch(it + 1);
        CP_COMMIT();
        CP_WAIT1();
        __syncthreads();

        const int s = it & 1;
        const float* As = sm + s * STAGE_FLOATS;
        const float* Bs = As + 128 * SA;

        // single per-tile TC accumulator (zeroed each tile)
        float acc[4][4][4];
#pragma unroll
        for (int i = 0; i < 4; i++)
#pragma unroll
            for (int j = 0; j < 4; j++)
#pragma unroll
                for (int q = 0; q < 4; q++) acc[i][j][q] = 0.f;

#pragma unroll
        for (int ks = 0; ks < 4; ++ks) {
            uint32_t ahi[4][4], alo[4][4], bhi[4][2], blo[4][2];
#pragma unroll
            for (int mi = 0; mi < 4; ++mi) {
                const int r = wm * 64 + mi * 16 + g;
                const int c = ks * 8 + tg;
                split1(As[r * SA + c],           ahi[mi][0], alo[mi][0]);
                split1(As[(r + 8) * SA + c],     ahi[mi][1], alo[mi][1]);
                split1(As[r * SA + c + 4],       ahi[mi][2], alo[mi][2]);
                split1(As[(r + 8) * SA + c + 4], ahi[mi][3], alo[mi][3]);
            }
#pragma unroll
            for (int ni = 0; ni < 4; ++ni) {
                const int n = wn * 32 + ni * 8 + g;
                const int k = ks * 8 + tg;
                split1(Bs[n * SA + k],     bhi[ni][0], blo[ni][0]);
                split1(Bs[n * SA + k + 4], bhi[ni][1], blo[ni][1]);
            }
#pragma unroll
            for (int mi = 0; mi < 4; ++mi)
#pragma unroll
                for (int ni = 0; ni < 4; ++ni) {
                    mma8(acc[mi][ni], ahi[mi], bhi[ni]);
                    mma8(acc[mi][ni], ahi[mi], blo[ni]);
                    mma8(acc[mi][ni], alo[mi], bhi[ni]);
                }
        }

        // drain tile partials into fp32 register sums
#pragma unroll
        for (int mi = 0; mi < 4; ++mi)
#pragma unroll
            for (int ni = 0; ni < 4; ++ni)
#pragma unroll
                for (int q = 0; q < 4; ++q)
                    sum[mi][ni][q] += acc[mi][ni][q];

        __syncthreads();
    }

    // ---- epilogue: sums -> SMEM cur tile [128 t][132], LIF scan ----
    float* cur = sm;   // 128*132*4 = 67584 <= 73728
#pragma unroll
    for (int mi = 0; mi < 4; ++mi)
#pragma unroll
        for (int ni = 0; ni < 4; ++ni) {
            const int r = wm * 64 + mi * 16 + g;
            const int c = wn * 32 + ni * 8 + tg * 2;
            cur[r * 132 + c]           = sum[mi][ni][0];
            cur[r * 132 + c + 1]       = sum[mi][ni][1];
            cur[(r + 8) * 132 + c]     = sum[mi][ni][2];
            cur[(r + 8) * 132 + c + 1] = sum[mi][ni][3];
        }
    __syncthreads();

    if (tid < 128) {
        float mem1 = 0.f;
        __nv_bfloat16* dst = g_spk + (size_t)b * 128 * N_HID + n0 + tid;
#pragma unroll 4
        for (int t = 0; t < T_STEPS; ++t) {
            const float cv = cur[t * 132 + tid];
            const float reset = (mem1 > 1.0f) ? 1.0f : 0.0f;
            mem1 = 0.95f * mem1 + cv - reset;
            dst[(size_t)t * N_HID] = __float2bfloat16((mem1 > 1.0f) ? 1.0f : 0.0f);
        }
    }
}

// ===================== K2: cur2 = spk @ W2^T ================================
__global__ __launch_bounds__(256)
void snn_gemm2(const float* __restrict__ W2)   // [N_OUT, N_HID]
{
    __shared__ float w2s[N_HID * 11];
    const int tid  = threadIdx.x;
    const int wid  = tid >> 5;
    const int lane = tid & 31;

    for (int i = tid; i < N_HID * N_OUT; i += 256) {
        const int h = i / N_OUT;
        const int o = i - h * N_OUT;
        w2s[h * 11 + o] = W2[o * N_HID + h];
    }
    __syncthreads();

    const size_t m = (size_t)blockIdx.x * 8 + wid;
    const __nv_bfloat16* srow = g_spk + m * N_HID;

    float acc[N_OUT];
#pragma unroll
    for (int o = 0; o < N_OUT; o++) acc[o] = 0.f;

#pragma unroll 4
    for (int j = 0; j < 32; ++j) {
        const int h = lane + j * 32;
        const float s = __bfloat162float(srow[h]);
        if (s != 0.f) {
#pragma unroll
            for (int o = 0; o < N_OUT; o++) acc[o] += w2s[h * 11 + o];
        }
    }

#pragma unroll
    for (int o = 0; o < N_OUT; o++) {
        acc[o] += __shfl_down_sync(0xffffffffu, acc[o], 16);
        acc[o] += __shfl_down_sync(0xffffffffu, acc[o], 8);
        acc[o] += __shfl_down_sync(0xffffffffu, acc[o], 4);
        acc[o] += __shfl_down_sync(0xffffffffu, acc[o], 2);
        acc[o] += __shfl_down_sync(0xffffffffu, acc[o], 1);
    }
    if (lane == 0) {
#pragma unroll
        for (int o = 0; o < N_OUT; o++) g_cur2[m * N_OUT + o] = acc[o];
    }
}

// ===================== K3: mem2 leaky integration ==========================
__global__ void snn_scan2(float* __restrict__ out)   // [T, B, N_OUT]
{
    const int id = blockIdx.x * 256 + threadIdx.x;
    if (id >= BATCH * N_OUT) return;
    const int bb = id / N_OUT;
    const int o  = id - bb * N_OUT;

    float m2 = 0.f;
    for (int t = 0; t < T_STEPS; ++t) {
        m2 = 0.95f * m2 + g_cur2[((size_t)bb * T_STEPS + t) * N_OUT + o];
        out[((size_t)t * BATCH + bb) * N_OUT + o] = m2;
    }
}

// ===================== launch ==============================================
extern "C" void kernel_launch(void* const* d_in, const int* in_sizes, int n_in,
                              void* d_out, int out_size)
{
    const float* x  = (const float*)d_in[0];   // [B, T, K_IN]
    const float* W1 = (const float*)d_in[1];   // [N_HID, K_IN]
    const float* W2 = (const float*)d_in[2];   // [N_OUT, N_HID]
    float* out = (float*)d_out;                // [T, B, N_OUT]

    cudaFuncSetAttribute(snn_gemm_spike,
                         cudaFuncAttributeMaxDynamicSharedMemorySize, GEMM_SMEM);

    dim3 grid1(N_HID / 128, M_TOTAL / 128);    // (8, 256)
    snn_gemm_spike<<<grid1, 256, GEMM_SMEM>>>(x, W1);
    snn_gemm2<<<M_TOTAL / 8, 256>>>(W2);
    snn_scan2<<<(BATCH * N_OUT + 255) / 256, 256>>>(out);
}